// round 4
// baseline (speedup 1.0000x reference)
#include <cuda_runtime.h>
#include <cuda_bf16.h>
#include <math.h>

// Problem constants
#define T_  256
#define B_  128
#define H_  1024
#define L_  4
#define MTOT (T_ * B_)   // 32768

#define NBLK 128         // persistent blocks (<= SM count, co-resident)
#define NTHR 256

// Scratch: precomputed input projections for current layer + double-buffered h.
__device__ float g_P[(size_t)MTOT * H_];
__device__ float g_h[2][B_ * H_];

// grid barrier state
__device__ volatile unsigned g_bar_gen = 0;
__device__ unsigned g_bar_cnt = 0;

__device__ __forceinline__ void grid_barrier()
{
    __syncthreads();
    if (threadIdx.x == 0) {
        unsigned gen = g_bar_gen;            // read BEFORE arriving
        __threadfence();                     // make this block's writes visible
        if (atomicAdd(&g_bar_cnt, 1) == NBLK - 1) {
            atomicExch(&g_bar_cnt, 0);
            __threadfence();
            g_bar_gen = gen + 1;             // release
        } else {
            while (g_bar_gen == gen) { }     // spin in L2
            __threadfence();
        }
    }
    __syncthreads();
}

// ---------------------------------------------------------------------------
// Kernel 1: per-layer precompute  P = X @ Wi^T + (bi + bh)
// Classic 128x128x8 register-blocked SGEMM, 256 threads, 8x8 per thread.
// ---------------------------------------------------------------------------
#define PBM 128
#define PBN 128
#define PBK 8

__global__ __launch_bounds__(256) void gemm_pre(
    const float* __restrict__ X, const float* __restrict__ W,
    const float* __restrict__ bi, const float* __restrict__ bh)
{
    __shared__ float As[PBK][PBM];
    __shared__ float Bs[PBK][PBN];

    const int m0 = blockIdx.y * PBM;
    const int n0 = blockIdx.x * PBN;
    const int tid = threadIdx.x;
    const int tx = tid & 15;
    const int ty = tid >> 4;

    const int lr = tid >> 1;
    const int lc = (tid & 1) * 4;

    const float* Xp = X + (size_t)(m0 + lr) * H_ + lc;
    const float* Wp = W + (size_t)(n0 + lr) * H_ + lc;

    float acc[8][8];
    #pragma unroll
    for (int i = 0; i < 8; i++)
        #pragma unroll
        for (int j = 0; j < 8; j++) acc[i][j] = 0.0f;

    for (int k0 = 0; k0 < H_; k0 += PBK) {
        float4 xa = *(const float4*)(Xp + k0);
        float4 wb = *(const float4*)(Wp + k0);
        __syncthreads();
        As[lc + 0][lr] = xa.x; As[lc + 1][lr] = xa.y;
        As[lc + 2][lr] = xa.z; As[lc + 3][lr] = xa.w;
        Bs[lc + 0][lr] = wb.x; Bs[lc + 1][lr] = wb.y;
        Bs[lc + 2][lr] = wb.z; Bs[lc + 3][lr] = wb.w;
        __syncthreads();

        #pragma unroll
        for (int kk = 0; kk < PBK; kk++) {
            float a[8], b[8];
            *(float4*)(a)     = *(const float4*)&As[kk][ty * 8];
            *(float4*)(a + 4) = *(const float4*)&As[kk][ty * 8 + 4];
            *(float4*)(b)     = *(const float4*)&Bs[kk][tx * 8];
            *(float4*)(b + 4) = *(const float4*)&Bs[kk][tx * 8 + 4];
            #pragma unroll
            for (int i = 0; i < 8; i++)
                #pragma unroll
                for (int j = 0; j < 8; j++)
                    acc[i][j] = fmaf(a[i], b[j], acc[i][j]);
        }
    }

    float bias[8];
    #pragma unroll
    for (int j = 0; j < 8; j++) {
        int n = n0 + tx * 8 + j;
        bias[j] = bi[n] + bh[n];
    }
    #pragma unroll
    for (int i = 0; i < 8; i++) {
        int m = m0 + ty * 8 + i;
        float* Pr = g_P + (size_t)m * H_ + n0 + tx * 8;
        #pragma unroll
        for (int j = 0; j < 8; j++) Pr[j] = acc[i][j] + bias[j];
    }
}

// ---------------------------------------------------------------------------
// Kernel 2: persistent recurrence, REGISTER-RESIDENT weights.
// 128 blocks x 256 threads. Block owns 8 output columns (n0 = bid*8).
// Thread (c = tid>>7, s = tid&127) holds Wh[n0+4c .. n0+4c+3][8s .. 8s+7]
// in 32 registers for the whole layer. Per batch row b it loads 8 h floats
// (2x LDG.128) and does 32 FFMA -> 4 partial dot products, which are
// reduced over the 128 k-slices (s) through SMEM.
//
// SMEM: partial[2][128 s][73] (o = bb*8 + 4c + j, o < 64; stride 73 makes
// both the STS (addr = 73*s + o, banks 9*s distinct) and the phase-2 LDS
// conflict-(nearly-)free.
// ---------------------------------------------------------------------------
#define PSTRIDE 73
#define RSM_FLOATS (2 * 128 * PSTRIDE)

__global__ __launch_bounds__(NTHR) void rnn_seq(
    const float* __restrict__ hx, const float* __restrict__ Wh,
    float* __restrict__ outx, float* __restrict__ hn)
{
    extern __shared__ float partial[];   // [2][128][PSTRIDE]

    const int tid = threadIdx.x;
    const int bid = blockIdx.x;
    const int n0  = bid * 8;
    const int c   = tid >> 7;          // 0/1: which 4 of the block's 8 cols
    const int s   = tid & 127;         // k-slice index (8 k per slice)

    // --- load this thread's W slice into registers (once per layer) ---
    float4 Wr[4][2];
    #pragma unroll
    for (int j = 0; j < 4; j++) {
        const float* wrow = Wh + (size_t)(n0 + 4 * c + j) * H_ + 8 * s;
        Wr[j][0] = *(const float4*)(wrow);
        Wr[j][1] = *(const float4*)(wrow + 4);
    }

    // --- init h: g_h[0] = hx ---
    {
        int i = bid * NTHR + tid;
        ((float4*)g_h[0])[i] = ((const float4*)hx)[i];
    }
    grid_barrier();

    const int o_base = 4 * c;          // column part of output index

    for (int t = 0; t < T_; t++) {
        const float* __restrict__ hprev = g_h[t & 1];
        float* __restrict__ hnext = g_h[(t + 1) & 1];
        const float* __restrict__ Pt = g_P + (size_t)t * B_ * H_;
        float* __restrict__ ox = outx + (size_t)t * B_ * H_;

        const float* hb = hprev + 8 * s;

        // prefetch b = 0
        float4 p0 = *(const float4*)(hb);
        float4 p1 = *(const float4*)(hb + 4);

        #pragma unroll 1
        for (int b = 0; b < B_; b++) {
            const float4 h0 = p0, h1 = p1;
            if (b < B_ - 1) {
                const float* nb = hb + (size_t)(b + 1) * H_;
                p0 = *(const float4*)(nb);
                p1 = *(const float4*)(nb + 4);
            }
            const int bb = b & 7;
            float* Pb = partial + ((b >> 3) & 1) * (128 * PSTRIDE)
                                + s * PSTRIDE + bb * 8 + o_base;
            #pragma unroll
            for (int j = 0; j < 4; j++) {
                float a = h0.x * Wr[j][0].x;
                float d = h0.y * Wr[j][0].y;
                a = fmaf(h0.z, Wr[j][0].z, a);
                d = fmaf(h0.w, Wr[j][0].w, d);
                a = fmaf(h1.x, Wr[j][1].x, a);
                d = fmaf(h1.y, Wr[j][1].y, d);
                a = fmaf(h1.z, Wr[j][1].z, a);
                d = fmaf(h1.w, Wr[j][1].w, d);
                Pb[j] = a + d;
            }

            if (bb == 7) {
                __syncthreads();
                // ---- phase 2: reduce over s for the strip just finished ----
                const int strip = b >> 3;
                const float* Pr = partial + (strip & 1) * (128 * PSTRIDE);
                const int o = tid >> 2;        // 0..63
                const int p = tid & 3;         // 0..3
                float s0 = 0.f, s1 = 0.f, s2 = 0.f, s3 = 0.f;
                #pragma unroll
                for (int q = 0; q < 32; q += 4) {
                    s0 += Pr[(p + 4 * (q + 0)) * PSTRIDE + o];
                    s1 += Pr[(p + 4 * (q + 1)) * PSTRIDE + o];
                    s2 += Pr[(p + 4 * (q + 2)) * PSTRIDE + o];
                    s3 += Pr[(p + 4 * (q + 3)) * PSTRIDE + o];
                }
                float sum = (s0 + s1) + (s2 + s3);
                sum += __shfl_xor_sync(0xffffffffu, sum, 1);
                sum += __shfl_xor_sync(0xffffffffu, sum, 2);
                if (p == 0) {
                    const int ob = strip * 8 + (o >> 3);   // batch row
                    const int on = n0 + (o & 7);           // hidden column
                    const size_t idx = (size_t)ob * H_ + on;
                    float v = tanhf(sum + Pt[idx]);
                    hnext[idx] = v;
                    ox[idx] = v;
                    if (t == T_ - 1) hn[idx] = v;
                }
            }
        }
        grid_barrier();
    }
}

// ---------------------------------------------------------------------------
// Launch: per layer: 1 precompute GEMM + 1 persistent recurrence kernel.
// 8 graph nodes total.
// ---------------------------------------------------------------------------
extern "C" void kernel_launch(void* const* d_in, const int* in_sizes, int n_in,
                              void* d_out, int out_size)
{
    const float* inputs = (const float*)d_in[0];   // [T,B,H]
    const float* hxs    = (const float*)d_in[1];   // [L,B,H]
    const float* W_ih   = (const float*)d_in[2];   // [L,H,H]
    const float* b_ih   = (const float*)d_in[3];   // [L,H]
    const float* W_hh   = (const float*)d_in[4];   // [L,H,H]
    const float* b_hh   = (const float*)d_in[5];   // [L,H]

    float* out  = (float*)d_out;
    float* outx = out;                               // [T,B,H]
    float* outh = out + (size_t)T_ * B_ * H_;        // [L,B,H]

    static bool attr_done = false;
    if (!attr_done) {
        cudaFuncSetAttribute(rnn_seq, cudaFuncAttributeMaxDynamicSharedMemorySize,
                             RSM_FLOATS * (int)sizeof(float));
        attr_done = true;
    }

    dim3 pre_grid(H_ / PBN, MTOT / PBM);             // (8, 256)

    for (int l = 0; l < L_; l++) {
        const float* x_l = (l == 0) ? inputs : outx;
        gemm_pre<<<pre_grid, 256>>>(x_l,
                                    W_ih + (size_t)l * H_ * H_,
                                    b_ih + (size_t)l * H_,
                                    b_hh + (size_t)l * H_);
        rnn_seq<<<NBLK, NTHR, RSM_FLOATS * sizeof(float)>>>(
            hxs + (size_t)l * B_ * H_,
            W_hh + (size_t)l * H_ * H_,
            outx,
            outh + (size_t)l * B_ * H_);
    }
}

// round 5
// speedup vs baseline: 2.2649x; 2.2649x over previous
#include <cuda_runtime.h>
#include <cuda_bf16.h>
#include <math.h>

// Problem constants
#define T_  256
#define B_  128
#define H_  1024
#define L_  4
#define MTOT (T_ * B_)   // 32768

#define NBLK 128         // persistent blocks (<= SM count, co-resident)
#define NTHR 256

// Scratch: precomputed input projections for current layer + double-buffered h.
__device__ float g_P[(size_t)MTOT * H_];
__device__ float g_h[2][B_ * H_];

// grid barrier state
__device__ volatile unsigned g_bar_gen = 0;
__device__ unsigned g_bar_cnt = 0;

__device__ __forceinline__ void grid_barrier()
{
    __syncthreads();
    if (threadIdx.x == 0) {
        unsigned gen = g_bar_gen;            // read BEFORE arriving
        __threadfence();                     // make this block's writes visible
        if (atomicAdd(&g_bar_cnt, 1) == NBLK - 1) {
            atomicExch(&g_bar_cnt, 0);
            __threadfence();
            g_bar_gen = gen + 1;             // release
        } else {
            while (g_bar_gen == gen) { }     // spin in L2
            __threadfence();
        }
    }
    __syncthreads();
}

// ---------------------------------------------------------------------------
// Kernel 1: per-layer precompute  P = X @ Wi^T + (bi + bh)
// Classic 128x128x8 register-blocked SGEMM, 256 threads, 8x8 per thread.
// ---------------------------------------------------------------------------
#define PBM 128
#define PBN 128
#define PBK 8

__global__ __launch_bounds__(256) void gemm_pre(
    const float* __restrict__ X, const float* __restrict__ W,
    const float* __restrict__ bi, const float* __restrict__ bh)
{
    __shared__ float As[PBK][PBM];
    __shared__ float Bs[PBK][PBN];

    const int m0 = blockIdx.y * PBM;
    const int n0 = blockIdx.x * PBN;
    const int tid = threadIdx.x;
    const int tx = tid & 15;
    const int ty = tid >> 4;

    const int lr = tid >> 1;
    const int lc = (tid & 1) * 4;

    const float* Xp = X + (size_t)(m0 + lr) * H_ + lc;
    const float* Wp = W + (size_t)(n0 + lr) * H_ + lc;

    float acc[8][8];
    #pragma unroll
    for (int i = 0; i < 8; i++)
        #pragma unroll
        for (int j = 0; j < 8; j++) acc[i][j] = 0.0f;

    for (int k0 = 0; k0 < H_; k0 += PBK) {
        float4 xa = *(const float4*)(Xp + k0);
        float4 wb = *(const float4*)(Wp + k0);
        __syncthreads();
        As[lc + 0][lr] = xa.x; As[lc + 1][lr] = xa.y;
        As[lc + 2][lr] = xa.z; As[lc + 3][lr] = xa.w;
        Bs[lc + 0][lr] = wb.x; Bs[lc + 1][lr] = wb.y;
        Bs[lc + 2][lr] = wb.z; Bs[lc + 3][lr] = wb.w;
        __syncthreads();

        #pragma unroll
        for (int kk = 0; kk < PBK; kk++) {
            float a[8], b[8];
            *(float4*)(a)     = *(const float4*)&As[kk][ty * 8];
            *(float4*)(a + 4) = *(const float4*)&As[kk][ty * 8 + 4];
            *(float4*)(b)     = *(const float4*)&Bs[kk][tx * 8];
            *(float4*)(b + 4) = *(const float4*)&Bs[kk][tx * 8 + 4];
            #pragma unroll
            for (int i = 0; i < 8; i++)
                #pragma unroll
                for (int j = 0; j < 8; j++)
                    acc[i][j] = fmaf(a[i], b[j], acc[i][j]);
        }
    }

    float bias[8];
    #pragma unroll
    for (int j = 0; j < 8; j++) {
        int n = n0 + tx * 8 + j;
        bias[j] = bi[n] + bh[n];
    }
    #pragma unroll
    for (int i = 0; i < 8; i++) {
        int m = m0 + ty * 8 + i;
        float* Pr = g_P + (size_t)m * H_ + n0 + tx * 8;
        #pragma unroll
        for (int j = 0; j < 8; j++) Pr[j] = acc[i][j] + bias[j];
    }
}

// ---------------------------------------------------------------------------
// Kernel 2: persistent recurrence, 2n x 2b thread tiles, XOR-swizzled SMEM.
// 128 blocks x 256 threads. Block owns 8 output cols (n0 = bid*8) x all 128 b.
// Warp w owns b-rows [16w, 16w+16); lane l: nq = l>>3 (n-pair), bq = l&7
// (b-pair). Thread computes outputs (n0+2nq+{0,1}) x (16w+2bq+{0,1}).
//
// SMEM (float4 units):
//   Ws4[8][256]   : W row n at k4-index (k4 ^ n)            (32 KB, per layer)
//   hbuf[2][128][16]: h row (local to warp region, 16 rows/warp) at
//                     k4-index (k4 ^ (row>>1))              (2 x 32 KB)
// All compute loads are LDS.128, conflict-free by the XOR swizzle.
// h staging is per-warp private -> __syncwarp only, no __syncthreads in the
// k loop.
// ---------------------------------------------------------------------------
#define SM4_TOTAL (2048 + 2 * 2048)          // float4 count = 96 KB

__global__ __launch_bounds__(NTHR, 1) void rnn_seq(
    const float* __restrict__ hx, const float* __restrict__ Wh,
    float* __restrict__ outx, float* __restrict__ hn)
{
    extern __shared__ float4 sm4[];
    float4* Ws4 = sm4;                 // [8][256]
    float4* hb0 = sm4 + 2048;          // [128][16]
    float4* hb1 = sm4 + 4096;

    const int tid = threadIdx.x;
    const int bid = blockIdx.x;
    const int n0  = bid * 8;

    const int w   = tid >> 5;
    const int l   = tid & 31;
    const int nq  = l >> 3;            // 0..3
    const int bq  = l & 7;             // 0..7
    const int lr  = l >> 4;            // 0..1 (staging row parity)
    const int k4l = l & 15;            // staging k4

    // --- load W slice into swizzled SMEM (once per layer) ---
    #pragma unroll
    for (int j = 0; j < 8; j++) {
        int g  = tid + NTHR * j;       // 0..2047
        int n  = g >> 8;               // 0..7
        int k4 = g & 255;              // 0..255
        Ws4[n * 256 + (k4 ^ n)] =
            ((const float4*)(Wh + (size_t)(n0 + n) * H_))[k4];
    }

    // --- init h: g_h[0] = hx ---
    {
        int i = bid * NTHR + tid;
        ((float4*)g_h[0])[i] = ((const float4*)hx)[i];
    }
    grid_barrier();   // also makes Ws4 visible block-wide

    const int wk0 = 2 * nq;
    const int wk1 = 2 * nq + 1;
    const float4* W0 = Ws4 + wk0 * 256;
    const float4* W1 = Ws4 + wk1 * 256;

    const int rb0 = 16 * w + 2 * bq;   // first of this thread's 2 b-rows

    for (int t = 0; t < T_; t++) {
        const float* __restrict__ hprev = g_h[t & 1];
        float* __restrict__ hnext = g_h[(t + 1) & 1];
        const float* __restrict__ Pt = g_P + (size_t)t * B_ * H_;
        float* __restrict__ ox = outx + (size_t)t * B_ * H_;

        // prefetch P values for this thread's 4 outputs (consumed at epilogue)
        float2 Pv0 = *(const float2*)&Pt[(size_t)rb0 * H_ + n0 + 2 * nq];
        float2 Pv1 = *(const float2*)&Pt[(size_t)(rb0 + 1) * H_ + n0 + 2 * nq];

        float a00 = 0.f, a01 = 0.f, a10 = 0.f, a11 = 0.f;  // a[jn][jb]

        // global h base for this lane's staging slots (rows 16w+lr+2i)
        const float* hgbase = hprev + (size_t)(16 * w + lr) * H_ + 4 * k4l;

        // prefetch chunk 0
        float4 pf[8];
        #pragma unroll
        for (int i = 0; i < 8; i++)
            pf[i] = *(const float4*)(hgbase + (size_t)(2 * i) * H_);

        #pragma unroll 1
        for (int kc = 0; kc < 16; kc++) {
            float4* hw = ((kc & 1) ? hb1 : hb0) + w * 256;   // warp region
            // stage prefetched chunk (swizzled): row r=lr+2i, key = r>>1 = i
            #pragma unroll
            for (int i = 0; i < 8; i++)
                hw[(lr + 2 * i) * 16 + (k4l ^ i)] = pf[i];
            __syncwarp();
            // prefetch next chunk
            if (kc < 15) {
                const float* ng = hgbase + (kc + 1) * 64;
                #pragma unroll
                for (int i = 0; i < 8; i++)
                    pf[i] = *(const float4*)(ng + (size_t)(2 * i) * H_);
            }
            // compute 16 k4-steps on this chunk
            const float4* Wp0 = W0 + kc * 16;
            const float4* Wp1 = W1 + kc * 16;
            const float4* h0p = hw + (2 * bq) * 16;
            const float4* h1p = hw + (2 * bq + 1) * 16;
            #pragma unroll
            for (int k4 = 0; k4 < 16; k4++) {
                float4 w0 = Wp0[k4 ^ wk0];
                float4 w1 = Wp1[k4 ^ wk1];
                float4 h0 = h0p[k4 ^ bq];
                float4 h1 = h1p[k4 ^ bq];
                a00 = fmaf(w0.x, h0.x, a00); a00 = fmaf(w0.y, h0.y, a00);
                a00 = fmaf(w0.z, h0.z, a00); a00 = fmaf(w0.w, h0.w, a00);
                a10 = fmaf(w1.x, h0.x, a10); a10 = fmaf(w1.y, h0.y, a10);
                a10 = fmaf(w1.z, h0.z, a10); a10 = fmaf(w1.w, h0.w, a10);
                a01 = fmaf(w0.x, h1.x, a01); a01 = fmaf(w0.y, h1.y, a01);
                a01 = fmaf(w0.z, h1.z, a01); a01 = fmaf(w0.w, h1.w, a01);
                a11 = fmaf(w1.x, h1.x, a11); a11 = fmaf(w1.y, h1.y, a11);
                a11 = fmaf(w1.z, h1.z, a11); a11 = fmaf(w1.w, h1.w, a11);
            }
        }

        // epilogue: add P, tanh, store (hnext + output x [+ hn on last step])
        {
            float v00 = tanhf(a00 + Pv0.x);   // (n+0, b+0)
            float v10 = tanhf(a10 + Pv0.y);   // (n+1, b+0)
            float v01 = tanhf(a01 + Pv1.x);   // (n+0, b+1)
            float v11 = tanhf(a11 + Pv1.y);   // (n+1, b+1)
            const size_t i0 = (size_t)rb0 * H_ + n0 + 2 * nq;
            const size_t i1 = i0 + H_;
            float2 r0 = make_float2(v00, v10);
            float2 r1 = make_float2(v01, v11);
            *(float2*)&hnext[i0] = r0;
            *(float2*)&hnext[i1] = r1;
            *(float2*)&ox[i0] = r0;
            *(float2*)&ox[i1] = r1;
            if (t == T_ - 1) {
                *(float2*)&hn[i0] = r0;
                *(float2*)&hn[i1] = r1;
            }
        }
        grid_barrier();
    }
}

// ---------------------------------------------------------------------------
// Launch: per layer: 1 precompute GEMM + 1 persistent recurrence kernel.
// 8 graph nodes total.
// ---------------------------------------------------------------------------
extern "C" void kernel_launch(void* const* d_in, const int* in_sizes, int n_in,
                              void* d_out, int out_size)
{
    const float* inputs = (const float*)d_in[0];   // [T,B,H]
    const float* hxs    = (const float*)d_in[1];   // [L,B,H]
    const float* W_ih   = (const float*)d_in[2];   // [L,H,H]
    const float* b_ih   = (const float*)d_in[3];   // [L,H]
    const float* W_hh   = (const float*)d_in[4];   // [L,H,H]
    const float* b_hh   = (const float*)d_in[5];   // [L,H]

    float* out  = (float*)d_out;
    float* outx = out;                               // [T,B,H]
    float* outh = out + (size_t)T_ * B_ * H_;        // [L,B,H]

    static bool attr_done = false;
    if (!attr_done) {
        cudaFuncSetAttribute(rnn_seq, cudaFuncAttributeMaxDynamicSharedMemorySize,
                             SM4_TOTAL * (int)sizeof(float4));
        attr_done = true;
    }

    dim3 pre_grid(H_ / PBN, MTOT / PBM);             // (8, 256)

    for (int l = 0; l < L_; l++) {
        const float* x_l = (l == 0) ? inputs : outx;
        gemm_pre<<<pre_grid, 256>>>(x_l,
                                    W_ih + (size_t)l * H_ * H_,
                                    b_ih + (size_t)l * H_,
                                    b_hh + (size_t)l * H_);
        rnn_seq<<<NBLK, NTHR, SM4_TOTAL * sizeof(float4)>>>(
            hxs + (size_t)l * B_ * H_,
            W_hh + (size_t)l * H_ * H_,
            outx,
            outh + (size_t)l * B_ * H_);
    }
}

// round 6
// speedup vs baseline: 2.5823x; 1.1402x over previous
#include <cuda_runtime.h>
#include <cuda_bf16.h>
#include <math.h>

// Problem constants
#define T_  256
#define B_  128
#define H_  1024
#define L_  4
#define MTOT (T_ * B_)   // 32768

#define NBLK 128         // persistent blocks (<= SM count, co-resident)
#define NTHR 256

// Scratch: precomputed input projections for current layer + double-buffered h.
__device__ float g_P[(size_t)MTOT * H_];
__device__ float g_h[2][B_ * H_];

// bf16 hi/lo split scratch for the tensor-core precompute GEMM
__device__ __nv_bfloat16 g_Xhi[(size_t)MTOT * H_];
__device__ __nv_bfloat16 g_Xlo[(size_t)MTOT * H_];
__device__ __nv_bfloat16 g_Whi[(size_t)H_ * H_];
__device__ __nv_bfloat16 g_Wlo[(size_t)H_ * H_];

// grid barrier state
__device__ volatile unsigned g_bar_gen = 0;
__device__ unsigned g_bar_cnt = 0;

__device__ __forceinline__ void grid_barrier()
{
    __syncthreads();
    if (threadIdx.x == 0) {
        unsigned gen = g_bar_gen;            // read BEFORE arriving
        __threadfence();                     // make this block's writes visible
        if (atomicAdd(&g_bar_cnt, 1) == NBLK - 1) {
            atomicExch(&g_bar_cnt, 0);
            __threadfence();
            g_bar_gen = gen + 1;             // release
        } else {
            while (g_bar_gen == gen) { }     // spin in L2
            __threadfence();
        }
    }
    __syncthreads();
}

// ---------------------------------------------------------------------------
// fp32 -> (hi, lo) bf16 split.  x ~= hi + lo, |lo| <= 2^-9 |x|.
// ---------------------------------------------------------------------------
__global__ __launch_bounds__(256) void split_bf16(
    const float* __restrict__ src,
    __nv_bfloat16* __restrict__ hi, __nv_bfloat16* __restrict__ lo, int n4)
{
    int i = blockIdx.x * 256 + threadIdx.x;
    if (i >= n4) return;
    float4 v = ((const float4*)src)[i];
    __nv_bfloat16 h0 = __float2bfloat16_rn(v.x);
    __nv_bfloat16 h1 = __float2bfloat16_rn(v.y);
    __nv_bfloat16 h2 = __float2bfloat16_rn(v.z);
    __nv_bfloat16 h3 = __float2bfloat16_rn(v.w);
    __nv_bfloat16 l0 = __float2bfloat16_rn(v.x - __bfloat162float(h0));
    __nv_bfloat16 l1 = __float2bfloat16_rn(v.y - __bfloat162float(h1));
    __nv_bfloat16 l2 = __float2bfloat16_rn(v.z - __bfloat162float(h2));
    __nv_bfloat16 l3 = __float2bfloat16_rn(v.w - __bfloat162float(h3));
    __nv_bfloat162* hp = (__nv_bfloat162*)hi;
    __nv_bfloat162* lp = (__nv_bfloat162*)lo;
    hp[2 * i]     = __nv_bfloat162{h0, h1};
    hp[2 * i + 1] = __nv_bfloat162{h2, h3};
    lp[2 * i]     = __nv_bfloat162{l0, l1};
    lp[2 * i + 1] = __nv_bfloat162{l2, l3};
}

// ---------------------------------------------------------------------------
// Tensor-core precompute GEMM:
//   P = Xhi@Whi^T + Xhi@Wlo^T + Xlo@Whi^T + (bi + bh)
// Block 128x128, BK=32 bf16, 96 k-chunks (3 segments x 32), 256 threads,
// 8 warps as 4(M) x 2(N); warp tile 32x64; mma.sync m16n8k16 bf16 f32-accum.
// SMEM tiles padded to 5x16B per row (stride-5 units -> conflict-free LDSM).
// ---------------------------------------------------------------------------
__device__ __forceinline__ unsigned smem_u32(const void* p)
{
    return (unsigned)__cvta_generic_to_shared(p);
}

__device__ __forceinline__ void ldsm_x4(unsigned addr, unsigned& r0, unsigned& r1,
                                        unsigned& r2, unsigned& r3)
{
    asm volatile("ldmatrix.sync.aligned.m8n8.x4.shared.b16 {%0,%1,%2,%3}, [%4];"
                 : "=r"(r0), "=r"(r1), "=r"(r2), "=r"(r3) : "r"(addr));
}

__device__ __forceinline__ void mma16816(float* d, const unsigned* a,
                                         unsigned b0, unsigned b1)
{
    asm volatile(
        "mma.sync.aligned.m16n8k16.row.col.f32.bf16.bf16.f32 "
        "{%0,%1,%2,%3},{%4,%5,%6,%7},{%8,%9},{%0,%1,%2,%3};"
        : "+f"(d[0]), "+f"(d[1]), "+f"(d[2]), "+f"(d[3])
        : "r"(a[0]), "r"(a[1]), "r"(a[2]), "r"(a[3]), "r"(b0), "r"(b1));
}

__global__ __launch_bounds__(256) void gemm_pre_bf16(
    const float* __restrict__ bi, const float* __restrict__ bh)
{
    __shared__ uint4 sA[2][128 * 5];
    __shared__ uint4 sB[2][128 * 5];
    __shared__ float sBias[128];

    const int m0 = blockIdx.y * 128;
    const int n0 = blockIdx.x * 128;
    const int tid = threadIdx.x;
    const int wid = tid >> 5;
    const int lane = tid & 31;
    const int warp_m = wid >> 1;       // 0..3
    const int warp_n = wid & 1;        // 0..1

    if (tid < 128) sBias[tid] = bi[n0 + tid] + bh[n0 + tid];

    const __nv_bfloat16* Aseg[3] = { g_Xhi, g_Xhi, g_Xlo };
    const __nv_bfloat16* Bseg[3] = { g_Whi, g_Wlo, g_Whi };

    // staging: thread handles 16B units (r0u, c0u) and (r0u+64, c0u)
    const int r0u = tid >> 2;          // 0..63
    const int c0u = tid & 3;           // 0..3
    const size_t aOff0 = (size_t)(m0 + r0u) * H_ + c0u * 8;
    const size_t aOff1 = aOff0 + (size_t)64 * H_;
    const size_t bOff0 = (size_t)(n0 + r0u) * H_ + c0u * 8;
    const size_t bOff1 = bOff0 + (size_t)64 * H_;

    float acc0[8][4], acc1[8][4];
    #pragma unroll
    for (int j = 0; j < 8; j++)
        #pragma unroll
        for (int q = 0; q < 4; q++) { acc0[j][q] = 0.f; acc1[j][q] = 0.f; }

    // prefetch chunk 0
    uint4 pa0 = *(const uint4*)(Aseg[0] + aOff0);
    uint4 pa1 = *(const uint4*)(Aseg[0] + aOff1);
    uint4 pb0 = *(const uint4*)(Bseg[0] + bOff0);
    uint4 pb1 = *(const uint4*)(Bseg[0] + bOff1);

    #pragma unroll 1
    for (int ci = 0; ci < 96; ci++) {
        uint4* bufA = sA[ci & 1];
        uint4* bufB = sB[ci & 1];
        bufA[r0u * 5 + c0u] = pa0;
        bufA[(r0u + 64) * 5 + c0u] = pa1;
        bufB[r0u * 5 + c0u] = pb0;
        bufB[(r0u + 64) * 5 + c0u] = pb1;
        __syncthreads();

        if (ci < 95) {
            const int cn = ci + 1;
            const int sg = cn >> 5;
            const size_t k2 = (size_t)(cn & 31) * 32;
            const __nv_bfloat16* A = Aseg[sg];
            const __nv_bfloat16* Bp = Bseg[sg];
            pa0 = *(const uint4*)(A + aOff0 + k2);
            pa1 = *(const uint4*)(A + aOff1 + k2);
            pb0 = *(const uint4*)(Bp + bOff0 + k2);
            pb1 = *(const uint4*)(Bp + bOff1 + k2);
        }

        const unsigned saA = smem_u32(bufA);
        const unsigned saB = smem_u32(bufB);

        #pragma unroll
        for (int ks = 0; ks < 2; ks++) {
            unsigned a0[4], a1[4];
            {
                const int row = warp_m * 32 + (lane & 7) + ((lane >> 3) & 1) * 8;
                const int cu = ks * 2 + (lane >> 4);
                ldsm_x4(saA + (unsigned)((row * 5 + cu) * 16),
                        a0[0], a0[1], a0[2], a0[3]);
                ldsm_x4(saA + (unsigned)(((row + 16) * 5 + cu) * 16),
                        a1[0], a1[1], a1[2], a1[3]);
            }
            unsigned b[4][4];
            {
                const int rb = warp_n * 64 + (lane & 7) + ((lane >> 4) & 1) * 8;
                const int cu = ks * 2 + ((lane >> 3) & 1);
                #pragma unroll
                for (int g = 0; g < 4; g++)
                    ldsm_x4(saB + (unsigned)(((rb + g * 16) * 5 + cu) * 16),
                            b[g][0], b[g][1], b[g][2], b[g][3]);
            }
            #pragma unroll
            for (int g = 0; g < 4; g++) {
                mma16816(acc0[2 * g],     a0, b[g][0], b[g][1]);
                mma16816(acc0[2 * g + 1], a0, b[g][2], b[g][3]);
                mma16816(acc1[2 * g],     a1, b[g][0], b[g][1]);
                mma16816(acc1[2 * g + 1], a1, b[g][2], b[g][3]);
            }
        }
        __syncthreads();
    }

    // epilogue: add bias, write fp32 P
    const int mrow = m0 + warp_m * 32 + (lane >> 2);
    const int ncol0 = warp_n * 64 + 2 * (lane & 3);
    #pragma unroll
    for (int i = 0; i < 2; i++) {
        const int r = mrow + i * 16;
        float* acc[8];
        #pragma unroll
        for (int j = 0; j < 8; j++) {
            const int cc = ncol0 + j * 8;       // col within block
            const float b0 = sBias[cc];
            const float b1 = sBias[cc + 1];
            const float* av = (i == 0) ? acc0[j] : acc1[j];
            float2 v0 = make_float2(av[0] + b0, av[1] + b1);
            float2 v1 = make_float2(av[2] + b0, av[3] + b1);
            *(float2*)&g_P[(size_t)r * H_ + n0 + cc] = v0;
            *(float2*)&g_P[(size_t)(r + 8) * H_ + n0 + cc] = v1;
        }
        (void)acc;
    }
}

// ---------------------------------------------------------------------------
// Kernel 2: persistent recurrence, 2n x 2b thread tiles, XOR-swizzled SMEM.
// (unchanged from round 5)
// ---------------------------------------------------------------------------
#define SM4_TOTAL (2048 + 2 * 2048)          // float4 count = 96 KB

__global__ __launch_bounds__(NTHR, 1) void rnn_seq(
    const float* __restrict__ hx, const float* __restrict__ Wh,
    float* __restrict__ outx, float* __restrict__ hn)
{
    extern __shared__ float4 sm4[];
    float4* Ws4 = sm4;                 // [8][256]
    float4* hb0 = sm4 + 2048;          // [128][16]
    float4* hb1 = sm4 + 4096;

    const int tid = threadIdx.x;
    const int bid = blockIdx.x;
    const int n0  = bid * 8;

    const int w   = tid >> 5;
    const int l   = tid & 31;
    const int nq  = l >> 3;            // 0..3
    const int bq  = l & 7;             // 0..7
    const int lr  = l >> 4;            // 0..1 (staging row parity)
    const int k4l = l & 15;            // staging k4

    // --- load W slice into swizzled SMEM (once per layer) ---
    #pragma unroll
    for (int j = 0; j < 8; j++) {
        int g  = tid + NTHR * j;       // 0..2047
        int n  = g >> 8;               // 0..7
        int k4 = g & 255;              // 0..255
        Ws4[n * 256 + (k4 ^ n)] =
            ((const float4*)(Wh + (size_t)(n0 + n) * H_))[k4];
    }

    // --- init h: g_h[0] = hx ---
    {
        int i = bid * NTHR + tid;
        ((float4*)g_h[0])[i] = ((const float4*)hx)[i];
    }
    grid_barrier();   // also makes Ws4 visible block-wide

    const int wk0 = 2 * nq;
    const int wk1 = 2 * nq + 1;
    const float4* W0 = Ws4 + wk0 * 256;
    const float4* W1 = Ws4 + wk1 * 256;

    const int rb0 = 16 * w + 2 * bq;   // first of this thread's 2 b-rows

    for (int t = 0; t < T_; t++) {
        const float* __restrict__ hprev = g_h[t & 1];
        float* __restrict__ hnext = g_h[(t + 1) & 1];
        const float* __restrict__ Pt = g_P + (size_t)t * B_ * H_;
        float* __restrict__ ox = outx + (size_t)t * B_ * H_;

        // prefetch P values for this thread's 4 outputs (consumed at epilogue)
        float2 Pv0 = *(const float2*)&Pt[(size_t)rb0 * H_ + n0 + 2 * nq];
        float2 Pv1 = *(const float2*)&Pt[(size_t)(rb0 + 1) * H_ + n0 + 2 * nq];

        float a00 = 0.f, a01 = 0.f, a10 = 0.f, a11 = 0.f;  // a[jn][jb]

        // global h base for this lane's staging slots (rows 16w+lr+2i)
        const float* hgbase = hprev + (size_t)(16 * w + lr) * H_ + 4 * k4l;

        // prefetch chunk 0
        float4 pf[8];
        #pragma unroll
        for (int i = 0; i < 8; i++)
            pf[i] = *(const float4*)(hgbase + (size_t)(2 * i) * H_);

        #pragma unroll 1
        for (int kc = 0; kc < 16; kc++) {
            float4* hw = ((kc & 1) ? hb1 : hb0) + w * 256;   // warp region
            // stage prefetched chunk (swizzled): row r=lr+2i, key = r>>1 = i
            #pragma unroll
            for (int i = 0; i < 8; i++)
                hw[(lr + 2 * i) * 16 + (k4l ^ i)] = pf[i];
            __syncwarp();
            // prefetch next chunk
            if (kc < 15) {
                const float* ng = hgbase + (kc + 1) * 64;
                #pragma unroll
                for (int i = 0; i < 8; i++)
                    pf[i] = *(const float4*)(ng + (size_t)(2 * i) * H_);
            }
            // compute 16 k4-steps on this chunk
            const float4* Wp0 = W0 + kc * 16;
            const float4* Wp1 = W1 + kc * 16;
            const float4* h0p = hw + (2 * bq) * 16;
            const float4* h1p = hw + (2 * bq + 1) * 16;
            #pragma unroll
            for (int k4 = 0; k4 < 16; k4++) {
                float4 w0 = Wp0[k4 ^ wk0];
                float4 w1 = Wp1[k4 ^ wk1];
                float4 h0 = h0p[k4 ^ bq];
                float4 h1 = h1p[k4 ^ bq];
                a00 = fmaf(w0.x, h0.x, a00); a00 = fmaf(w0.y, h0.y, a00);
                a00 = fmaf(w0.z, h0.z, a00); a00 = fmaf(w0.w, h0.w, a00);
                a10 = fmaf(w1.x, h0.x, a10); a10 = fmaf(w1.y, h0.y, a10);
                a10 = fmaf(w1.z, h0.z, a10); a10 = fmaf(w1.w, h0.w, a10);
                a01 = fmaf(w0.x, h1.x, a01); a01 = fmaf(w0.y, h1.y, a01);
                a01 = fmaf(w0.z, h1.z, a01); a01 = fmaf(w0.w, h1.w, a01);
                a11 = fmaf(w1.x, h1.x, a11); a11 = fmaf(w1.y, h1.y, a11);
                a11 = fmaf(w1.z, h1.z, a11); a11 = fmaf(w1.w, h1.w, a11);
            }
        }

        // epilogue: add P, tanh, store (hnext + output x [+ hn on last step])
        {
            float v00 = tanhf(a00 + Pv0.x);   // (n+0, b+0)
            float v10 = tanhf(a10 + Pv0.y);   // (n+1, b+0)
            float v01 = tanhf(a01 + Pv1.x);   // (n+0, b+1)
            float v11 = tanhf(a11 + Pv1.y);   // (n+1, b+1)
            const size_t i0 = (size_t)rb0 * H_ + n0 + 2 * nq;
            const size_t i1 = i0 + H_;
            float2 r0 = make_float2(v00, v10);
            float2 r1 = make_float2(v01, v11);
            *(float2*)&hnext[i0] = r0;
            *(float2*)&hnext[i1] = r1;
            *(float2*)&ox[i0] = r0;
            *(float2*)&ox[i1] = r1;
            if (t == T_ - 1) {
                *(float2*)&hn[i0] = r0;
                *(float2*)&hn[i1] = r1;
            }
        }
        grid_barrier();
    }
}

// ---------------------------------------------------------------------------
// Launch: per layer: split X, split W, tensor-core GEMM, persistent
// recurrence. 16 graph nodes total.
// ---------------------------------------------------------------------------
extern "C" void kernel_launch(void* const* d_in, const int* in_sizes, int n_in,
                              void* d_out, int out_size)
{
    const float* inputs = (const float*)d_in[0];   // [T,B,H]
    const float* hxs    = (const float*)d_in[1];   // [L,B,H]
    const float* W_ih   = (const float*)d_in[2];   // [L,H,H]
    const float* b_ih   = (const float*)d_in[3];   // [L,H]
    const float* W_hh   = (const float*)d_in[4];   // [L,H,H]
    const float* b_hh   = (const float*)d_in[5];   // [L,H]

    float* out  = (float*)d_out;
    float* outx = out;                               // [T,B,H]
    float* outh = out + (size_t)T_ * B_ * H_;        // [L,B,H]

    static bool attr_done = false;
    if (!attr_done) {
        cudaFuncSetAttribute(rnn_seq, cudaFuncAttributeMaxDynamicSharedMemorySize,
                             SM4_TOTAL * (int)sizeof(float4));
        attr_done = true;
    }

    __nv_bfloat16* xhi; cudaGetSymbolAddress((void**)&xhi, g_Xhi);
    __nv_bfloat16* xlo; cudaGetSymbolAddress((void**)&xlo, g_Xlo);
    __nv_bfloat16* whi; cudaGetSymbolAddress((void**)&whi, g_Whi);
    __nv_bfloat16* wlo; cudaGetSymbolAddress((void**)&wlo, g_Wlo);

    const int nX4 = MTOT * H_ / 4;                   // 8,388,608
    const int nW4 = H_ * H_ / 4;                     // 262,144

    dim3 pre_grid(H_ / 128, MTOT / 128);             // (8, 256)

    for (int l = 0; l < L_; l++) {
        const float* x_l = (l == 0) ? inputs : outx;
        split_bf16<<<nX4 / 256, 256>>>(x_l, xhi, xlo, nX4);
        split_bf16<<<nW4 / 256, 256>>>(W_ih + (size_t)l * H_ * H_, whi, wlo, nW4);
        gemm_pre_bf16<<<pre_grid, 256>>>(b_ih + (size_t)l * H_,
                                         b_hh + (size_t)l * H_);
        rnn_seq<<<NBLK, NTHR, SM4_TOTAL * sizeof(float4)>>>(
            hxs + (size_t)l * B_ * H_,
            W_hh + (size_t)l * H_ * H_,
            outx,
            outh + (size_t)l * B_ * H_);
    }
}